// round 1
// baseline (speedup 1.0000x reference)
#include <cuda_runtime.h>
#include <math.h>

// ---------------------------------------------------------------------------
// SpectralFeatureExtractor:
//   feats[b, c*4 + {0,1,2,3}] = {amp0, amp1, phase0, phase1} of top-2 |rfft24|
//   h   = gelu_exact(feats @ W1 + b1)      [4096 x 512]
//   out = h @ W2 + b2                      [4096 x 512] -> d_out (4096,1,512)
// ---------------------------------------------------------------------------

#define B_ROWS   4096
#define C_CH     64
#define T_LEN    256
#define NROWS    (B_ROWS * C_CH)   // 262144
#define NFFT     24
#define FBINS    12                // bins 1..12
#define DIN      256               // C*TOPK*2
#define FEAT     512

// scratch (allocation-free: __device__ globals)
__device__ float g_feats[B_ROWS * DIN];     // 4 MB
__device__ float g_h[B_ROWS * FEAT];        // 8 MB

// ---------------------------------------------------------------------------
// Kernel 1: spectral features. One thread per (b,c) row.
// ---------------------------------------------------------------------------
__global__ __launch_bounds__(256) void feats_kernel(
    const float* __restrict__ x, float* __restrict__ feats)
{
    __shared__ float s_ct[NFFT];
    __shared__ float s_st[NFFT];
    int t = threadIdx.x;
    if (t < NFFT) {
        float s, c;
        sincospif((float)t / 12.0f, &s, &c);   // angle = pi * t / 12 = 2*pi*t/24
        s_ct[t] = c;
        s_st[t] = s;
    }
    __syncthreads();

    int row = blockIdx.x * 256 + t;            // < NROWS

    // copy twiddles to registers
    float ctr[NFFT], str[NFFT];
#pragma unroll
    for (int m = 0; m < NFFT; m++) { ctr[m] = s_ct[m]; str[m] = s_st[m]; }

    // load first 24 samples of this row (row stride = 1024B, 16B aligned)
    const float4* xp = reinterpret_cast<const float4*>(x + (size_t)row * T_LEN);
    float xs[NFFT];
#pragma unroll
    for (int i = 0; i < 6; i++) {
        float4 v = xp[i];
        xs[4*i + 0] = v.x; xs[4*i + 1] = v.y;
        xs[4*i + 2] = v.z; xs[4*i + 3] = v.w;
    }

    // 12-bin DFT (k = 1..12): X[k] = sum_n x[n] * exp(-2*pi*i*k*n/24)
    float re[FBINS], im[FBINS];
#pragma unroll
    for (int k = 0; k < FBINS; k++) { re[k] = 0.0f; im[k] = 0.0f; }
#pragma unroll
    for (int n = 0; n < NFFT; n++) {
        float xv = xs[n];
#pragma unroll
        for (int k = 1; k <= FBINS; k++) {
            const int m = (k * n) % NFFT;       // compile-time constant index
            re[k-1] = fmaf(xv,  ctr[m], re[k-1]);
            im[k-1] = fmaf(xv, -str[m], im[k-1]);
        }
    }

    float mag2[FBINS];
#pragma unroll
    for (int k = 0; k < FBINS; k++) mag2[k] = re[k]*re[k] + im[k]*im[k];

    // top-2 (descending, ties -> lower index, matching lax.top_k)
    int i1 = 0; float m1 = mag2[0];
#pragma unroll
    for (int k = 1; k < FBINS; k++) if (mag2[k] > m1) { m1 = mag2[k]; i1 = k; }
    int i2 = (i1 == 0) ? 1 : 0; float m2 = mag2[i2];
#pragma unroll
    for (int k = 0; k < FBINS; k++)
        if (k != i1 && mag2[k] > m2) { m2 = mag2[k]; i2 = k; }

    float r1 = 0.f, q1 = 0.f, r2 = 0.f, q2 = 0.f;
#pragma unroll
    for (int k = 0; k < FBINS; k++) {
        if (k == i1) { r1 = re[k]; q1 = im[k]; }
        if (k == i2) { r2 = re[k]; q2 = im[k]; }
    }

    float4 o;
    o.x = sqrtf(m1);            // amp0
    o.y = sqrtf(m2);            // amp1
    o.z = atan2f(q1, r1);       // phase0
    o.w = atan2f(q2, r2);       // phase1
    reinterpret_cast<float4*>(feats + (size_t)row * 4)[0] = o;
}

// ---------------------------------------------------------------------------
// Packed fp32x2 helpers (Blackwell FFMA2 — 2x FFMA lanes per issue)
// ---------------------------------------------------------------------------
__device__ __forceinline__ unsigned long long pack2(float lo, float hi) {
    unsigned long long r;
    asm("mov.b64 %0, {%1, %2};" : "=l"(r) : "f"(lo), "f"(hi));
    return r;
}
__device__ __forceinline__ void fma2(unsigned long long& d,
                                     unsigned long long a, unsigned long long b) {
    asm("fma.rn.f32x2 %0, %1, %2, %0;" : "+l"(d) : "l"(a), "l"(b));
}
__device__ __forceinline__ float2 unpack2(unsigned long long v) {
    float2 r;
    asm("mov.b64 {%0, %1}, %2;" : "=f"(r.x), "=f"(r.y) : "l"(v));
    return r;
}

__device__ __forceinline__ float gelu_exact(float v) {
    return 0.5f * v * (1.0f + erff(v * 0.70710678118654752f));
}

// ---------------------------------------------------------------------------
// Kernel 2/3: C = act(A[M,K] @ W[K,N] + bias), N = 512.
// BM=BN=64, BK=16, 256 threads, 4x4 micro-tile via fp32x2 FMAs.
// ---------------------------------------------------------------------------
template <int K, bool DO_GELU>
__global__ __launch_bounds__(256) void mlp_gemm(
    const float* __restrict__ A, const float* __restrict__ W,
    const float* __restrict__ bias, float* __restrict__ C)
{
    constexpr int N = FEAT;
    __shared__ float As[16][68];   // [k][m], padded (68*4=272B rows, 16B aligned)
    __shared__ float Bs[16][64];   // [k][n]

    const int t  = threadIdx.x;
    const int tx = t & 15;         // 0..15 -> n
    const int ty = t >> 4;         // 0..15 -> m
    const int brow = blockIdx.y * 64;
    const int bcol = blockIdx.x * 64;

    // global load coords (fixed across K-tiles)
    const int ar = t >> 2;                 // A row within tile (0..63)
    const int ak = (t & 3) * 4;            // k segment
    const int bk = t >> 4;                 // W k row within tile (0..15)
    const int bc = (t & 15) * 4;           // W col segment

    unsigned long long acc[4][2];
#pragma unroll
    for (int i = 0; i < 4; i++) { acc[i][0] = pack2(0.f, 0.f); acc[i][1] = pack2(0.f, 0.f); }

    for (int k0 = 0; k0 < K; k0 += 16) {
        float4 av = reinterpret_cast<const float4*>(
            A + (size_t)(brow + ar) * K + k0 + ak)[0];
        float4 bv = reinterpret_cast<const float4*>(
            W + (size_t)(k0 + bk) * N + bcol + bc)[0];
        __syncthreads();
        As[ak + 0][ar] = av.x;
        As[ak + 1][ar] = av.y;
        As[ak + 2][ar] = av.z;
        As[ak + 3][ar] = av.w;
        reinterpret_cast<float4*>(&Bs[bk][bc])[0] = bv;
        __syncthreads();

#pragma unroll
        for (int kk = 0; kk < 16; kk++) {
            float4 a = reinterpret_cast<const float4*>(&As[kk][ty * 4])[0];
            ulonglong2 b = reinterpret_cast<const ulonglong2*>(&Bs[kk][tx * 4])[0];
            unsigned long long a0 = pack2(a.x, a.x);
            unsigned long long a1 = pack2(a.y, a.y);
            unsigned long long a2 = pack2(a.z, a.z);
            unsigned long long a3 = pack2(a.w, a.w);
            fma2(acc[0][0], a0, b.x); fma2(acc[0][1], a0, b.y);
            fma2(acc[1][0], a1, b.x); fma2(acc[1][1], a1, b.y);
            fma2(acc[2][0], a2, b.x); fma2(acc[2][1], a2, b.y);
            fma2(acc[3][0], a3, b.x); fma2(acc[3][1], a3, b.y);
        }
    }

    const int col0 = bcol + tx * 4;
    float4 bb = reinterpret_cast<const float4*>(bias + col0)[0];
#pragma unroll
    for (int i = 0; i < 4; i++) {
        float2 p0 = unpack2(acc[i][0]);
        float2 p1 = unpack2(acc[i][1]);
        float4 o;
        o.x = p0.x + bb.x; o.y = p0.y + bb.y;
        o.z = p1.x + bb.z; o.w = p1.y + bb.w;
        if (DO_GELU) {
            o.x = gelu_exact(o.x); o.y = gelu_exact(o.y);
            o.z = gelu_exact(o.z); o.w = gelu_exact(o.w);
        }
        reinterpret_cast<float4*>(C + (size_t)(brow + ty * 4 + i) * N + col0)[0] = o;
    }
}

// ---------------------------------------------------------------------------
extern "C" void kernel_launch(void* const* d_in, const int* in_sizes, int n_in,
                              void* d_out, int out_size)
{
    const float* x  = (const float*)d_in[0];
    const float* W1 = (const float*)d_in[1];
    const float* b1 = (const float*)d_in[2];
    const float* W2 = (const float*)d_in[3];
    const float* b2 = (const float*)d_in[4];
    float* out = (float*)d_out;

    float* feats = nullptr;
    float* h = nullptr;
    cudaGetSymbolAddress((void**)&feats, g_feats);
    cudaGetSymbolAddress((void**)&h, g_h);

    feats_kernel<<<NROWS / 256, 256>>>(x, feats);

    dim3 grid(FEAT / 64, B_ROWS / 64);   // (8, 64)
    mlp_gemm<DIN,  true ><<<grid, 256>>>(feats, W1, b1, h);
    mlp_gemm<FEAT, false><<<grid, 256>>>(h,     W2, b2, out);
}

// round 3
// speedup vs baseline: 1.4415x; 1.4415x over previous
#include <cuda_runtime.h>
#include <cuda_bf16.h>
#include <math.h>
#include <stdint.h>

#define B_ROWS   4096
#define T_LEN    256
#define NROWS    (B_ROWS * 64)
#define NFFT     24
#define FBINS    12
#define DIN      256
#define FEAT     512
#define K1P      (3 * DIN)     // 768
#define K2P      (3 * FEAT)    // 1536

// ---------------- scratch (__device__ globals; no allocs) ----------------
__device__ __nv_bfloat16 g_a1[B_ROWS * K1P];    // [Ah | Ah | Al]      6 MB
__device__ __nv_bfloat16 g_h2[B_ROWS * K2P];    // [Hh | Hh | Hl]     12 MB
__device__ __nv_bfloat16 g_w1t[FEAT * K1P];     // [W1h | W1l | W1h]^T
__device__ __nv_bfloat16 g_w2t[FEAT * K2P];     // [W2h | W2l | W2h]^T

// ---------------- helpers ----------------
__device__ __forceinline__ uint32_t smem_u32(const void* p) {
    uint32_t a;
    asm("{ .reg .u64 t; cvta.to.shared.u64 t, %1; cvt.u32.u64 %0, t; }"
        : "=r"(a) : "l"(p));
    return a;
}
__device__ __forceinline__ void cp16(uint32_t dst, const void* src) {
    asm volatile("cp.async.cg.shared.global [%0], [%1], 16;"
                 :: "r"(dst), "l"(src));
}
__device__ __forceinline__ void cp_commit() {
    asm volatile("cp.async.commit_group;");
}
template <int N>
__device__ __forceinline__ void cp_wait() {
    asm volatile("cp.async.wait_group %0;" :: "n"(N));
}
#define LDSM4(r, addr)                                                        \
    asm volatile("ldmatrix.sync.aligned.m8n8.x4.shared.b16 {%0,%1,%2,%3}, [%4];" \
                 : "=r"((r)[0]), "=r"((r)[1]), "=r"((r)[2]), "=r"((r)[3])     \
                 : "r"(addr))
#define MMA16816(d, a, b0, b1)                                                \
    asm volatile(                                                             \
        "mma.sync.aligned.m16n8k16.row.col.f32.bf16.bf16.f32 "                \
        "{%0,%1,%2,%3}, {%4,%5,%6,%7}, {%8,%9}, {%0,%1,%2,%3};"               \
        : "+f"((d)[0]), "+f"((d)[1]), "+f"((d)[2]), "+f"((d)[3])              \
        : "r"((a)[0]), "r"((a)[1]), "r"((a)[2]), "r"((a)[3]),                 \
          "r"(b0), "r"(b1))

// packed fp32x2 helpers
__device__ __forceinline__ unsigned long long pack2(float lo, float hi) {
    unsigned long long r;
    asm("mov.b64 %0, {%1, %2};" : "=l"(r) : "f"(lo), "f"(hi));
    return r;
}
__device__ __forceinline__ void fma2(unsigned long long& d,
                                     unsigned long long a, unsigned long long b) {
    asm("fma.rn.f32x2 %0, %1, %2, %0;" : "+l"(d) : "l"(a), "l"(b));
}
__device__ __forceinline__ float2 unpack2(unsigned long long v) {
    float2 r;
    asm("mov.b64 {%0, %1}, %2;" : "=f"(r.x), "=f"(r.y) : "l"(v));
    return r;
}
__device__ __forceinline__ float gelu_exact(float v) {
    return 0.5f * v * (1.0f + erff(v * 0.70710678118654752f));
}
__device__ __forceinline__ void split_bf16(float v, __nv_bfloat16& h, __nv_bfloat16& l) {
    h = __float2bfloat16_rn(v);
    l = __float2bfloat16_rn(v - __bfloat162float(h));
}

// ---------------------------------------------------------------------------
// Kernel 1: spectral features -> A' = [Ah | Ah | Al]  [4096 x 768] bf16
// ---------------------------------------------------------------------------
__global__ __launch_bounds__(256) void feats_kernel(
    const float* __restrict__ x, __nv_bfloat16* __restrict__ a1)
{
    __shared__ float2 s_tw[NFFT];
    int t = threadIdx.x;
    if (t < NFFT) {
        float s, c;
        sincospif((float)t / 12.0f, &s, &c);
        s_tw[t] = make_float2(c, -s);
    }
    __syncthreads();

    int row = blockIdx.x * 256 + t;

    unsigned long long tw[NFFT];
#pragma unroll
    for (int m = 0; m < NFFT; m++) { float2 v = s_tw[m]; tw[m] = pack2(v.x, v.y); }

    const float4* xp = reinterpret_cast<const float4*>(x + (size_t)row * T_LEN);
    float xs[NFFT];
#pragma unroll
    for (int i = 0; i < 6; i++) {
        float4 v = xp[i];
        xs[4*i + 0] = v.x; xs[4*i + 1] = v.y;
        xs[4*i + 2] = v.z; xs[4*i + 3] = v.w;
    }

    unsigned long long acc[FBINS];
#pragma unroll
    for (int k = 0; k < FBINS; k++) acc[k] = pack2(0.f, 0.f);
#pragma unroll
    for (int n = 0; n < NFFT; n++) {
        unsigned long long xv = pack2(xs[n], xs[n]);
#pragma unroll
        for (int k = 1; k <= FBINS; k++) {
            const int m = (k * n) % NFFT;
            fma2(acc[k-1], xv, tw[m]);
        }
    }

    float re[FBINS], im[FBINS], mag2[FBINS];
#pragma unroll
    for (int k = 0; k < FBINS; k++) {
        float2 p = unpack2(acc[k]);
        re[k] = p.x; im[k] = p.y;
        mag2[k] = p.x*p.x + p.y*p.y;
    }

    int i1 = 0; float m1 = mag2[0];
#pragma unroll
    for (int k = 1; k < FBINS; k++) if (mag2[k] > m1) { m1 = mag2[k]; i1 = k; }
    int i2 = (i1 == 0) ? 1 : 0; float m2 = mag2[i2];
#pragma unroll
    for (int k = 0; k < FBINS; k++)
        if (k != i1 && mag2[k] > m2) { m2 = mag2[k]; i2 = k; }

    float r1 = 0.f, q1 = 0.f, r2 = 0.f, q2 = 0.f;
#pragma unroll
    for (int k = 0; k < FBINS; k++) {
        if (k == i1) { r1 = re[k]; q1 = im[k]; }
        if (k == i2) { r2 = re[k]; q2 = im[k]; }
    }

    float o0 = sqrtf(m1);
    float o1 = sqrtf(m2);
    float o2 = atan2f(q1, r1);
    float o3 = atan2f(q2, r2);

    __nv_bfloat16 h0,h1,h2,h3,l0,l1,l2,l3;
    split_bf16(o0,h0,l0); split_bf16(o1,h1,l1);
    split_bf16(o2,h2,l2); split_bf16(o3,h3,l3);

    int b = row >> 6, c = row & 63;
    __nv_bfloat16* base = a1 + (size_t)b * K1P + c * 4;
    __nv_bfloat162 hp0{h0, h1}, hp1{h2, h3}, lp0{l0, l1}, lp1{l2, l3};
    reinterpret_cast<__nv_bfloat162*>(base)[0]       = hp0;   // seg0 (Ah)
    reinterpret_cast<__nv_bfloat162*>(base)[1]       = hp1;
    reinterpret_cast<__nv_bfloat162*>(base + DIN)[0] = hp0;   // seg1 (Ah)
    reinterpret_cast<__nv_bfloat162*>(base + DIN)[1] = hp1;
    reinterpret_cast<__nv_bfloat162*>(base + 2*DIN)[0] = lp0; // seg2 (Al)
    reinterpret_cast<__nv_bfloat162*>(base + 2*DIN)[1] = lp1;
}

// ---------------------------------------------------------------------------
// W prep: W[K][N] fp32 -> Wt'[N][3K] bf16 layout [Wh | Wl | Wh] per row
// ---------------------------------------------------------------------------
__global__ __launch_bounds__(256) void prep_w(
    const float* __restrict__ W, __nv_bfloat16* __restrict__ Tp, int K, int N)
{
    __shared__ float sm[32][33];
    int k0 = blockIdx.y * 32, n0 = blockIdx.x * 32;
    int tx = threadIdx.x & 31, ty = threadIdx.x >> 5;   // (32, 8)
#pragma unroll
    for (int i = ty; i < 32; i += 8)
        sm[i][tx] = W[(size_t)(k0 + i) * N + n0 + tx];
    __syncthreads();
#pragma unroll
    for (int r = ty; r < 32; r += 8) {
        float v = sm[tx][r];
        __nv_bfloat16 h, l; split_bf16(v, h, l);
        size_t rb = (size_t)(n0 + r) * (3 * K);
        Tp[rb + k0 + tx]         = h;   // seg0: Wh
        Tp[rb + K + k0 + tx]     = l;   // seg1: Wl
        Tp[rb + 2 * K + k0 + tx] = h;   // seg2: Wh
    }
}

// ---------------------------------------------------------------------------
// bf16 HMMA GEMM: C[4096, 512] = act(A'[M, KTOT] @ Bt'[512, KTOT]^T + bias)
// CTA tile 128x128, 8 warps of 64x32, mma.sync m16n8k16, 2-stage cp.async.
// ---------------------------------------------------------------------------
#define KPAD 40                 // bf16 elems per smem row (80 B, conflict-free)
#define TSZ  (128 * KPAD)

template <int KTOT, bool SPLIT_OUT>
__global__ __launch_bounds__(256, 1) void hmma_gemm(
    const __nv_bfloat16* __restrict__ A, const __nv_bfloat16* __restrict__ Bt,
    const float* __restrict__ bias,
    float* __restrict__ outF, __nv_bfloat16* __restrict__ outS)
{
    __shared__ __align__(128) __nv_bfloat16 sA[2][TSZ];
    __shared__ __align__(128) __nv_bfloat16 sB[2][TSZ];

    const int tid  = threadIdx.x;
    const int lane = tid & 31;
    const int wid  = tid >> 5;
    const int brow = blockIdx.y * 128;
    const int bcol = blockIdx.x * 128;
    const int m0 = (wid & 1) * 64;      // warp m-offset within CTA tile
    const int n0 = (wid >> 1) * 32;     // warp n-offset

    // copy coords: thread -> row (0..127), 2x 16B chunks
    const int cr = tid >> 1;
    const int cc = (tid & 1) * 16;

    float c[4][4][4];
#pragma unroll
    for (int i = 0; i < 4; i++)
#pragma unroll
        for (int j = 0; j < 4; j++)
#pragma unroll
            for (int q = 0; q < 4; q++) c[i][j][q] = 0.0f;

    auto copy_tile = [&](int kt, int buf) {
        uint32_t da = smem_u32(&sA[buf][cr * KPAD + cc]);
        uint32_t db = smem_u32(&sB[buf][cr * KPAD + cc]);
        const __nv_bfloat16* ga = A  + (size_t)(brow + cr) * KTOT + kt * 32 + cc;
        const __nv_bfloat16* gb = Bt + (size_t)(bcol + cr) * KTOT + kt * 32 + cc;
        cp16(da,      ga);
        cp16(da + 16, ga + 8);
        cp16(db,      gb);
        cp16(db + 16, gb + 8);
    };

    constexpr int NT = KTOT / 32;
    copy_tile(0, 0);
    cp_commit();

    // precompute ldmatrix lane addressing pieces
    const int a_row = lane & 15;             // 0..15
    const int a_kh  = (lane >> 4) * 8;       // 0 / 8
    const int b_row = (lane & 7) + ((lane >> 4) << 3);   // 0..15
    const int b_kh  = ((lane >> 3) & 1) << 3;            // 0 / 8

    for (int kt = 0; kt < NT; kt++) {
        const int buf = kt & 1;
        if (kt + 1 < NT) {
            copy_tile(kt + 1, buf ^ 1);
            cp_commit();
            cp_wait<1>();
        } else {
            cp_wait<0>();
        }
        __syncthreads();

#pragma unroll
        for (int ks = 0; ks < 2; ks++) {
            uint32_t a[4][4];
#pragma unroll
            for (int i = 0; i < 4; i++) {
                uint32_t addr = smem_u32(
                    &sA[buf][(m0 + i * 16 + a_row) * KPAD + ks * 16 + a_kh]);
                LDSM4(a[i], addr);
            }
            uint32_t bf[2][4];
#pragma unroll
            for (int j = 0; j < 2; j++) {
                uint32_t addr = smem_u32(
                    &sB[buf][(n0 + j * 16 + b_row) * KPAD + ks * 16 + b_kh]);
                LDSM4(bf[j], addr);
            }
#pragma unroll
            for (int i = 0; i < 4; i++) {
#pragma unroll
                for (int jn = 0; jn < 4; jn++) {
                    const int j = jn >> 1;
                    if (jn & 1) MMA16816(c[i][jn], a[i], bf[j][2], bf[j][3]);
                    else        MMA16816(c[i][jn], a[i], bf[j][0], bf[j][1]);
                }
            }
        }
        __syncthreads();
    }

    // ---- epilogue ----
#pragma unroll
    for (int i = 0; i < 4; i++) {
        const int gm = brow + m0 + i * 16 + (lane >> 2);
#pragma unroll
        for (int jn = 0; jn < 4; jn++) {
            const int gc = bcol + n0 + jn * 8 + ((lane & 3) << 1);
            float2 bb = *reinterpret_cast<const float2*>(bias + gc);
#pragma unroll
            for (int rh = 0; rh < 2; rh++) {
                const int m = gm + rh * 8;
                float v0 = c[i][jn][rh * 2 + 0] + bb.x;
                float v1 = c[i][jn][rh * 2 + 1] + bb.y;
                if (SPLIT_OUT) {
                    v0 = gelu_exact(v0);
                    v1 = gelu_exact(v1);
                    __nv_bfloat16 h0,l0,h1,l1;
                    split_bf16(v0, h0, l0); split_bf16(v1, h1, l1);
                    __nv_bfloat162 hp{h0, h1}, lp{l0, l1};
                    __nv_bfloat16* ro = outS + (size_t)m * K2P + gc;
                    *reinterpret_cast<__nv_bfloat162*>(ro)            = hp;
                    *reinterpret_cast<__nv_bfloat162*>(ro + FEAT)     = hp;
                    *reinterpret_cast<__nv_bfloat162*>(ro + 2*FEAT)   = lp;
                } else {
                    float2 o{v0, v1};
                    *reinterpret_cast<float2*>(outF + (size_t)m * FEAT + gc) = o;
                }
            }
        }
    }
}

// ---------------------------------------------------------------------------
extern "C" void kernel_launch(void* const* d_in, const int* in_sizes, int n_in,
                              void* d_out, int out_size)
{
    const float* x  = (const float*)d_in[0];
    const float* W1 = (const float*)d_in[1];
    const float* b1 = (const float*)d_in[2];
    const float* W2 = (const float*)d_in[3];
    const float* b2 = (const float*)d_in[4];
    float* out = (float*)d_out;

    __nv_bfloat16 *a1, *h2, *w1t, *w2t;
    cudaGetSymbolAddress((void**)&a1,  g_a1);
    cudaGetSymbolAddress((void**)&h2,  g_h2);
    cudaGetSymbolAddress((void**)&w1t, g_w1t);
    cudaGetSymbolAddress((void**)&w2t, g_w2t);

    prep_w<<<dim3(FEAT / 32, DIN / 32),  256>>>(W1, w1t, DIN,  FEAT);
    prep_w<<<dim3(FEAT / 32, FEAT / 32), 256>>>(W2, w2t, FEAT, FEAT);
    feats_kernel<<<NROWS / 256, 256>>>(x, a1);

    dim3 grid(FEAT / 128, B_ROWS / 128);   // (4, 32)
    hmma_gemm<K1P, true ><<<grid, 256>>>(a1, w1t, b1, nullptr, h2);
    hmma_gemm<K2P, false><<<grid, 256>>>(h2, w2t, b2, out, nullptr);
}

// round 4
// speedup vs baseline: 1.5089x; 1.0468x over previous
#include <cuda_runtime.h>
#include <cuda_bf16.h>
#include <math.h>
#include <stdint.h>

#define B_ROWS   4096
#define T_LEN    256
#define NROWS    (B_ROWS * 64)
#define NFFT     24
#define FBINS    12
#define DIN      256
#define FEAT     512
#define K1P      (3 * DIN)     // 768
#define K2P      (3 * FEAT)    // 1536

// ---------------- scratch (__device__ globals; no allocs) ----------------
__device__ __nv_bfloat16 g_a1[B_ROWS * K1P];    // [Ah | Ah | Al]      6 MB
__device__ __nv_bfloat16 g_h2[B_ROWS * K2P];    // [Hh | Hh | Hl]     12 MB
__device__ __nv_bfloat16 g_w1t[FEAT * K1P];     // [W1h | W1l | W1h]^T
__device__ __nv_bfloat16 g_w2t[FEAT * K2P];     // [W2h | W2l | W2h]^T

// ---------------- helpers ----------------
__device__ __forceinline__ uint32_t smem_u32(const void* p) {
    uint32_t a;
    asm("{ .reg .u64 t; cvta.to.shared.u64 t, %1; cvt.u32.u64 %0, t; }"
        : "=r"(a) : "l"(p));
    return a;
}
__device__ __forceinline__ void cp16(uint32_t dst, const void* src) {
    asm volatile("cp.async.cg.shared.global [%0], [%1], 16;"
                 :: "r"(dst), "l"(src));
}
__device__ __forceinline__ void cp_commit() {
    asm volatile("cp.async.commit_group;");
}
template <int N>
__device__ __forceinline__ void cp_wait() {
    asm volatile("cp.async.wait_group %0;" :: "n"(N));
}
#define LDSM4(r, addr)                                                        \
    asm volatile("ldmatrix.sync.aligned.m8n8.x4.shared.b16 {%0,%1,%2,%3}, [%4];" \
                 : "=r"((r)[0]), "=r"((r)[1]), "=r"((r)[2]), "=r"((r)[3])     \
                 : "r"(addr))
#define MMA16816(d, a, b0, b1)                                                \
    asm volatile(                                                             \
        "mma.sync.aligned.m16n8k16.row.col.f32.bf16.bf16.f32 "                \
        "{%0,%1,%2,%3}, {%4,%5,%6,%7}, {%8,%9}, {%0,%1,%2,%3};"               \
        : "+f"((d)[0]), "+f"((d)[1]), "+f"((d)[2]), "+f"((d)[3])              \
        : "r"((a)[0]), "r"((a)[1]), "r"((a)[2]), "r"((a)[3]),                 \
          "r"(b0), "r"(b1))

// packed fp32x2 helpers
__device__ __forceinline__ unsigned long long pack2(float lo, float hi) {
    unsigned long long r;
    asm("mov.b64 %0, {%1, %2};" : "=l"(r) : "f"(lo), "f"(hi));
    return r;
}
__device__ __forceinline__ void fma2(unsigned long long& d,
                                     unsigned long long a, unsigned long long b) {
    asm("fma.rn.f32x2 %0, %1, %2, %0;" : "+l"(d) : "l"(a), "l"(b));
}
__device__ __forceinline__ float2 unpack2(unsigned long long v) {
    float2 r;
    asm("mov.b64 {%0, %1}, %2;" : "=f"(r.x), "=f"(r.y) : "l"(v));
    return r;
}
__device__ __forceinline__ float gelu_exact(float v) {
    return 0.5f * v * (1.0f + erff(v * 0.70710678118654752f));
}
__device__ __forceinline__ void split_bf16(float v, __nv_bfloat16& h, __nv_bfloat16& l) {
    h = __float2bfloat16_rn(v);
    l = __float2bfloat16_rn(v - __bfloat162float(h));
}

// ---------------------------------------------------------------------------
// Kernel 1: spectral features -> A' = [Ah | Ah | Al]  [4096 x 768] bf16
// ---------------------------------------------------------------------------
__global__ __launch_bounds__(256) void feats_kernel(
    const float* __restrict__ x, __nv_bfloat16* __restrict__ a1)
{
    __shared__ float2 s_tw[NFFT];
    int t = threadIdx.x;
    if (t < NFFT) {
        float s, c;
        sincospif((float)t / 12.0f, &s, &c);
        s_tw[t] = make_float2(c, -s);
    }
    __syncthreads();

    int row = blockIdx.x * 256 + t;

    unsigned long long tw[NFFT];
#pragma unroll
    for (int m = 0; m < NFFT; m++) { float2 v = s_tw[m]; tw[m] = pack2(v.x, v.y); }

    const float4* xp = reinterpret_cast<const float4*>(x + (size_t)row * T_LEN);
    float xs[NFFT];
#pragma unroll
    for (int i = 0; i < 6; i++) {
        float4 v = xp[i];
        xs[4*i + 0] = v.x; xs[4*i + 1] = v.y;
        xs[4*i + 2] = v.z; xs[4*i + 3] = v.w;
    }

    unsigned long long acc[FBINS];
#pragma unroll
    for (int k = 0; k < FBINS; k++) acc[k] = pack2(0.f, 0.f);
#pragma unroll
    for (int n = 0; n < NFFT; n++) {
        unsigned long long xv = pack2(xs[n], xs[n]);
#pragma unroll
        for (int k = 1; k <= FBINS; k++) {
            const int m = (k * n) % NFFT;
            fma2(acc[k-1], xv, tw[m]);
        }
    }

    float re[FBINS], im[FBINS], mag2[FBINS];
#pragma unroll
    for (int k = 0; k < FBINS; k++) {
        float2 p = unpack2(acc[k]);
        re[k] = p.x; im[k] = p.y;
        mag2[k] = p.x*p.x + p.y*p.y;
    }

    int i1 = 0; float m1 = mag2[0];
#pragma unroll
    for (int k = 1; k < FBINS; k++) if (mag2[k] > m1) { m1 = mag2[k]; i1 = k; }
    int i2 = (i1 == 0) ? 1 : 0; float m2 = mag2[i2];
#pragma unroll
    for (int k = 0; k < FBINS; k++)
        if (k != i1 && mag2[k] > m2) { m2 = mag2[k]; i2 = k; }

    float r1 = 0.f, q1 = 0.f, r2 = 0.f, q2 = 0.f;
#pragma unroll
    for (int k = 0; k < FBINS; k++) {
        if (k == i1) { r1 = re[k]; q1 = im[k]; }
        if (k == i2) { r2 = re[k]; q2 = im[k]; }
    }

    float o0 = sqrtf(m1);
    float o1 = sqrtf(m2);
    float o2 = atan2f(q1, r1);
    float o3 = atan2f(q2, r2);

    __nv_bfloat16 h0,h1,h2,h3,l0,l1,l2,l3;
    split_bf16(o0,h0,l0); split_bf16(o1,h1,l1);
    split_bf16(o2,h2,l2); split_bf16(o3,h3,l3);

    int b = row >> 6, c = row & 63;
    __nv_bfloat16* base = a1 + (size_t)b * K1P + c * 4;
    __nv_bfloat162 hp0{h0, h1}, hp1{h2, h3}, lp0{l0, l1}, lp1{l2, l3};
    reinterpret_cast<__nv_bfloat162*>(base)[0]         = hp0;
    reinterpret_cast<__nv_bfloat162*>(base)[1]         = hp1;
    reinterpret_cast<__nv_bfloat162*>(base + DIN)[0]   = hp0;
    reinterpret_cast<__nv_bfloat162*>(base + DIN)[1]   = hp1;
    reinterpret_cast<__nv_bfloat162*>(base + 2*DIN)[0] = lp0;
    reinterpret_cast<__nv_bfloat162*>(base + 2*DIN)[1] = lp1;
}

// ---------------------------------------------------------------------------
// W prep: W[K][N] fp32 -> Wt'[N][3K] bf16 layout [Wh | Wl | Wh] per row
// ---------------------------------------------------------------------------
__global__ __launch_bounds__(256) void prep_w(
    const float* __restrict__ W, __nv_bfloat16* __restrict__ Tp, int K, int N)
{
    __shared__ float sm[32][33];
    int k0 = blockIdx.y * 32, n0 = blockIdx.x * 32;
    int tx = threadIdx.x & 31, ty = threadIdx.x >> 5;
#pragma unroll
    for (int i = ty; i < 32; i += 8)
        sm[i][tx] = W[(size_t)(k0 + i) * N + n0 + tx];
    __syncthreads();
#pragma unroll
    for (int r = ty; r < 32; r += 8) {
        float v = sm[tx][r];
        __nv_bfloat16 h, l; split_bf16(v, h, l);
        size_t rb = (size_t)(n0 + r) * (3 * K);
        Tp[rb + k0 + tx]         = h;
        Tp[rb + K + k0 + tx]     = l;
        Tp[rb + 2 * K + k0 + tx] = h;
    }
}

// ---------------------------------------------------------------------------
// bf16 HMMA GEMM, multistage:
//   CTA tile 128x64, 8 warps (warp tile 32x32), KC=32, 6-stage cp.async ring.
//   Grid (N/64, M/128) = (8, 32) = 256 CTAs; 2 CTAs/SM.
// ---------------------------------------------------------------------------
#define KPAD    40                       // elems per smem row (80 B)
#define A_ELS   (128 * KPAD)             // 5120 elems
#define B_ELS   (64 * KPAD)              // 2560 elems
#define STG_ELS (A_ELS + B_ELS)          // 7680 elems = 15360 B
#define NSTAGE  6
#define SMEM_BYTES (NSTAGE * STG_ELS * 2)   // 92160

template <int KTOT, bool SPLIT_OUT>
__global__ __launch_bounds__(256, 2) void hmma_gemm(
    const __nv_bfloat16* __restrict__ A, const __nv_bfloat16* __restrict__ Bt,
    const float* __restrict__ bias,
    float* __restrict__ outF, __nv_bfloat16* __restrict__ outS)
{
    extern __shared__ __nv_bfloat16 sm[];

    const int tid  = threadIdx.x;
    const int lane = tid & 31;
    const int wid  = tid >> 5;
    const int brow = blockIdx.y * 128;
    const int bcol = blockIdx.x * 64;
    const int m0 = (wid & 3) * 32;       // warp m-offset
    const int n0 = (wid >> 2) * 32;      // warp n-offset

    // copy coords
    const int a_cr = tid >> 1;           // A row 0..127
    const int a_cc = (tid & 1) * 16;     // A col elem (2x cp16)
    const int b_cr = tid >> 2;           // B row 0..63
    const int b_cc = (tid & 3) * 8;      // B col elem (1x cp16)

    const __nv_bfloat16* gA = A  + (size_t)(brow + a_cr) * KTOT + a_cc;
    const __nv_bfloat16* gB = Bt + (size_t)(bcol + b_cr) * KTOT + b_cc;
    const uint32_t sA0 = smem_u32(&sm[a_cr * KPAD + a_cc]);
    const uint32_t sB0 = smem_u32(&sm[A_ELS + b_cr * KPAD + b_cc]);

    auto copy_tile = [&](int kt, int buf) {
        const uint32_t so = buf * (STG_ELS * 2);   // byte offset
        const __nv_bfloat16* ga = gA + kt * 32;
        cp16(sA0 + so,      ga);
        cp16(sA0 + so + 16, ga + 8);
        cp16(sB0 + so,      gB + kt * 32);
    };

    constexpr int NT = KTOT / 32;

    // prologue: fill stages 0..4
#pragma unroll
    for (int p = 0; p < NSTAGE - 1; p++) {
        if (p < NT) copy_tile(p, p);
        cp_commit();
    }

    float c[2][4][4];
#pragma unroll
    for (int i = 0; i < 2; i++)
#pragma unroll
        for (int j = 0; j < 4; j++)
#pragma unroll
            for (int q = 0; q < 4; q++) c[i][j][q] = 0.0f;

    // ldmatrix lane addressing
    const int a_row = lane & 15;
    const int a_kh  = (lane >> 4) * 8;
    const int b_row = (lane & 7) + ((lane >> 4) << 3);
    const int b_kh  = ((lane >> 3) & 1) << 3;

    // per-warp smem byte offsets (within stage 0)
    uint32_t aAddr[2], bAddr[2];
#pragma unroll
    for (int i = 0; i < 2; i++)
        aAddr[i] = smem_u32(&sm[(m0 + i * 16 + a_row) * KPAD + a_kh]);
#pragma unroll
    for (int j = 0; j < 2; j++)
        bAddr[j] = smem_u32(&sm[A_ELS + (n0 + j * 16 + b_row) * KPAD + b_kh]);

    int buf = 0, nbuf = NSTAGE - 1;
    for (int kt = 0; kt < NT; kt++) {
        cp_wait<NSTAGE - 2>();
        __syncthreads();

        const int nk = kt + NSTAGE - 1;
        if (nk < NT) copy_tile(nk, nbuf);
        cp_commit();
        if (++nbuf == NSTAGE) nbuf = 0;

        const uint32_t so = buf * (STG_ELS * 2);
#pragma unroll
        for (int ks = 0; ks < 2; ks++) {
            uint32_t a[2][4], bf[2][4];
#pragma unroll
            for (int i = 0; i < 2; i++) LDSM4(a[i], aAddr[i] + so + ks * 32);
#pragma unroll
            for (int j = 0; j < 2; j++) LDSM4(bf[j], bAddr[j] + so + ks * 32);
#pragma unroll
            for (int i = 0; i < 2; i++) {
#pragma unroll
                for (int jn = 0; jn < 4; jn++) {
                    const int j = jn >> 1;
                    if (jn & 1) MMA16816(c[i][jn], a[i], bf[j][2], bf[j][3]);
                    else        MMA16816(c[i][jn], a[i], bf[j][0], bf[j][1]);
                }
            }
        }
        if (++buf == NSTAGE) buf = 0;
    }

    // ---- epilogue ----
#pragma unroll
    for (int i = 0; i < 2; i++) {
        const int gm = brow + m0 + i * 16 + (lane >> 2);
#pragma unroll
        for (int jn = 0; jn < 4; jn++) {
            const int gc = bcol + n0 + jn * 8 + ((lane & 3) << 1);
            float2 bb = *reinterpret_cast<const float2*>(bias + gc);
#pragma unroll
            for (int rh = 0; rh < 2; rh++) {
                const int m = gm + rh * 8;
                float v0 = c[i][jn][rh * 2 + 0] + bb.x;
                float v1 = c[i][jn][rh * 2 + 1] + bb.y;
                if (SPLIT_OUT) {
                    v0 = gelu_exact(v0);
                    v1 = gelu_exact(v1);
                    __nv_bfloat16 h0,l0,h1,l1;
                    split_bf16(v0, h0, l0); split_bf16(v1, h1, l1);
                    __nv_bfloat162 hp{h0, h1}, lp{l0, l1};
                    __nv_bfloat16* ro = outS + (size_t)m * K2P + gc;
                    *reinterpret_cast<__nv_bfloat162*>(ro)          = hp;
                    *reinterpret_cast<__nv_bfloat162*>(ro + FEAT)   = hp;
                    *reinterpret_cast<__nv_bfloat162*>(ro + 2*FEAT) = lp;
                } else {
                    float2 o{v0, v1};
                    *reinterpret_cast<float2*>(outF + (size_t)m * FEAT + gc) = o;
                }
            }
        }
    }
}

// ---------------------------------------------------------------------------
extern "C" void kernel_launch(void* const* d_in, const int* in_sizes, int n_in,
                              void* d_out, int out_size)
{
    const float* x  = (const float*)d_in[0];
    const float* W1 = (const float*)d_in[1];
    const float* b1 = (const float*)d_in[2];
    const float* W2 = (const float*)d_in[3];
    const float* b2 = (const float*)d_in[4];
    float* out = (float*)d_out;

    __nv_bfloat16 *a1, *h2, *w1t, *w2t;
    cudaGetSymbolAddress((void**)&a1,  g_a1);
    cudaGetSymbolAddress((void**)&h2,  g_h2);
    cudaGetSymbolAddress((void**)&w1t, g_w1t);
    cudaGetSymbolAddress((void**)&w2t, g_w2t);

    cudaFuncSetAttribute(hmma_gemm<K1P, true>,
                         cudaFuncAttributeMaxDynamicSharedMemorySize, SMEM_BYTES);
    cudaFuncSetAttribute(hmma_gemm<K2P, false>,
                         cudaFuncAttributeMaxDynamicSharedMemorySize, SMEM_BYTES);

    prep_w<<<dim3(FEAT / 32, DIN / 32),  256>>>(W1, w1t, DIN,  FEAT);
    prep_w<<<dim3(FEAT / 32, FEAT / 32), 256>>>(W2, w2t, FEAT, FEAT);
    feats_kernel<<<NROWS / 256, 256>>>(x, a1);

    dim3 grid(FEAT / 64, B_ROWS / 128);   // (8, 32)
    hmma_gemm<K1P, true ><<<grid, 256, SMEM_BYTES>>>(a1, w1t, b1, nullptr, h2);
    hmma_gemm<K2P, false><<<grid, 256, SMEM_BYTES>>>(h2, w2t, b2, out, nullptr);
}